// round 10
// baseline (speedup 1.0000x reference)
#include <cuda_runtime.h>
#include <cuda_bf16.h>

#define W_IMG 640
#define H_IMG 480
#define HW_IMG (W_IMG * H_IMG)
#define NSWEEPS 3
#define ILP 4

// Per-pixel packed winner: high 32 = point index+1 (last-write-wins key), low 32 =
// float bits of that point's depth. 0 = empty. Zero-init at load; resolve_kernel
// restores zeros after reading (invariant across graph replays).
__device__ __align__(16) unsigned long long g_pack[HW_IMG];

// ---- packed f32x2 helpers ----
#define FMA2(d, a, b, c) \
    asm("fma.rn.f32x2 %0, %1, %2, %3;" : "=l"(d) : "l"(a), "l"(b), "l"(c))
#define MUL2(d, a, b) \
    asm("mul.rn.f32x2 %0, %1, %2;" : "=l"(d) : "l"(a), "l"(b))

__device__ __forceinline__ unsigned long long pack2(float lo, float hi) {
    unsigned long long d;
    asm("mov.b64 %0, {%1, %2};" : "=l"(d)
        : "r"(__float_as_uint(lo)), "r"(__float_as_uint(hi)));
    return d;
}
__device__ __forceinline__ void unpack2(unsigned long long s, float& lo, float& hi) {
    unsigned int a, b;
    asm("mov.b64 {%0, %1}, %2;" : "=r"(a), "=r"(b) : "l"(s));
    lo = __uint_as_float(a);
    hi = __uint_as_float(b);
}

// MUFU.RSQ — keep rsqrt off the FMA pipe.
__device__ __forceinline__ float rsqrt_approx(float x) {
    float y;
    asm("rsqrt.approx.f32 %0, %1;" : "=f"(y) : "f"(x));
    return y;
}
// rcp.approx + 1 Newton step: ~full fp32, used once per point.
__device__ __forceinline__ float rcp_nr(float x) {
    float y;
    asm("rcp.approx.f32 %0, %1;" : "=f"(y) : "f"(x));
    return y * fmaf(-x, y, 2.0f);
}

// Per-point Jacobi state: A packed by row pairs, V rows 2&3 packed together.
struct PtState {
    unsigned long long A2[2][4];
    unsigned long long VP[4];
};

__device__ __forceinline__ void init_state(PtState& S, const float* P,
                                           float2 p0, float2 p1, float cf) {
#pragma unroll
    for (int j = 0; j < 4; j++) {
        float a0 = fmaf(p0.x, P[8 + j],  -P[0 + j]);
        float a1 = fmaf(p0.y, P[8 + j],  -P[4 + j]);
        float a2 = cf * fmaf(p1.x, P[20 + j], -P[12 + j]);
        float a3 = cf * fmaf(p1.y, P[20 + j], -P[16 + j]);
        S.A2[0][j] = pack2(a0, a1);
        S.A2[1][j] = pack2(a2, a3);
    }
    S.VP[0] = pack2(0.f, 0.f);
    S.VP[1] = pack2(0.f, 0.f);
    S.VP[2] = pack2(1.f, 0.f);
    S.VP[3] = pack2(0.f, 1.f);
}

// One Jacobi rotation on column pair (p, q). p,q are compile-time after unroll.
__device__ __forceinline__ void jacobi_rot(PtState& S, int p, int q) {
    const unsigned long long Z2 = 0ull;
    unsigned long long al2 = Z2, be2 = Z2, ga2 = Z2;
#pragma unroll
    for (int h = 0; h < 2; h++) {
        FMA2(al2, S.A2[h][p], S.A2[h][p], al2);
        FMA2(be2, S.A2[h][q], S.A2[h][q], be2);
        FMA2(ga2, S.A2[h][p], S.A2[h][q], ga2);
    }
    float alo, ahi, blo, bhi, glo, ghi;
    unpack2(al2, alo, ahi);
    unpack2(be2, blo, bhi);
    unpack2(ga2, glo, ghi);
    float al = alo + ahi, be = blo + bhi, ga = glo + ghi;

    // u = be-al, w = 2*ga, (c,s) ∝ (|u| + sqrt(u^2+w^2), w*sgn(u)).
    // Approx rsqrt keeps (c,s) an exact SCALED rotation; the common column
    // scale cancels in the final v2/v3 ratio.
    float u  = be - al;
    float w  = ga + ga;
    float zz = fmaf(u, u, w * w);
    float h_ = zz * rsqrt_approx(zz);               // sqrt(u^2+w^2), MUFU
    float d  = fabsf(u) + h_;
    float sr = __uint_as_float(__float_as_uint(w) ^
                               (__float_as_uint(u) & 0x80000000u));
    float rn = rsqrt_approx(fmaf(d, d, sr * sr));   // MUFU
    bool  ok = zz > 0.0f;                           // degenerate pair guard
    float c  = ok ? d * rn  : 1.0f;
    float s  = ok ? sr * rn : 0.0f;

    unsigned long long c2  = pack2(c, c);
    unsigned long long s2  = pack2(s, s);
    unsigned long long ns2 = pack2(-s, -s);
#pragma unroll
    for (int h = 0; h < 2; h++) {
        unsigned long long ap = S.A2[h][p], aq = S.A2[h][q], t;
        MUL2(t, ns2, aq); FMA2(S.A2[h][p], c2, ap, t);
        MUL2(t, s2,  ap); FMA2(S.A2[h][q], c2, aq, t);
    }
    {
        unsigned long long vp = S.VP[p], vq = S.VP[q], t;
        MUL2(t, ns2, vq); FMA2(S.VP[p], c2, vp, t);
        MUL2(t, s2,  vp); FMA2(S.VP[q], c2, vq, t);
    }
}

// Smallest-norm column -> depth value after clips + strict (0,30) filter.
__device__ __forceinline__ float finalize(PtState& S) {
    const unsigned long long Z2 = 0ull;
    float best = 3.4e38f;
    unsigned long long bestvp = S.VP[0];
#pragma unroll
    for (int j = 0; j < 4; j++) {
        unsigned long long acc = Z2;
#pragma unroll
        for (int h = 0; h < 2; h++) FMA2(acc, S.A2[h][j], S.A2[h][j], acc);
        float lo, hi;
        unpack2(acc, lo, hi);
        float t = lo + hi;
        if (t < best) { best = t; bestvp = S.VP[j]; }
    }
    float v2, v3;
    unpack2(bestvp, v2, v3);
    float zraw = v2 * rcp_nr(v3);
    float pc   = fminf(fmaxf(zraw, -1000.0f), 1000.0f);
    float zc   = fminf(fmaxf(pc, 0.0f), 30.0f);
    return (zc > 0.0f && zc < 30.0f) ? zc : 0.0f;
}

// ILP=4: four independent Jacobi chains per thread hide each other's
// MUFU/FMA latency (R7 showed IPC~0.57 at ILP=2 — still 40% latency-stalled).
__global__ void __launch_bounds__(128)
tri_kernel(const float* __restrict__ T,
           const float* __restrict__ K0,
           const float* __restrict__ K1,
           const float* __restrict__ mconf,
           const float* __restrict__ kp0,
           const float* __restrict__ kp1,
           float* __restrict__ out, int N) {
    int t  = blockIdx.x * blockDim.x + threadIdx.x;
    int n0 = t * ILP;
    if (n0 >= N) return;
    bool full = (n0 + ILP - 1) < N;

    float2 p0[ILP], p1[ILP];
    float  cf[ILP];
    if (full) {
        float4 a0 = reinterpret_cast<const float4*>(kp0)[t * 2 + 0];
        float4 a1 = reinterpret_cast<const float4*>(kp0)[t * 2 + 1];
        float4 b0 = reinterpret_cast<const float4*>(kp1)[t * 2 + 0];
        float4 b1 = reinterpret_cast<const float4*>(kp1)[t * 2 + 1];
        float4 cc = reinterpret_cast<const float4*>(mconf)[t];
        p0[0] = make_float2(a0.x, a0.y); p0[1] = make_float2(a0.z, a0.w);
        p0[2] = make_float2(a1.x, a1.y); p0[3] = make_float2(a1.z, a1.w);
        p1[0] = make_float2(b0.x, b0.y); p1[1] = make_float2(b0.z, b0.w);
        p1[2] = make_float2(b1.x, b1.y); p1[3] = make_float2(b1.z, b1.w);
        cf[0] = cc.x; cf[1] = cc.y; cf[2] = cc.z; cf[3] = cc.w;
    } else {
#pragma unroll
        for (int i = 0; i < ILP; i++) {
            int n = min(n0 + i, N - 1);
            p0[i] = reinterpret_cast<const float2*>(kp0)[n];
            p1[i] = reinterpret_cast<const float2*>(kp1)[n];
            cf[i] = mconf[n];
        }
    }

    // Projection matrices (warp-uniform loads -> L1 broadcast; dead after init).
    float P[24];
#pragma unroll
    for (int r = 0; r < 3; r++) {
#pragma unroll
        for (int c = 0; c < 3; c++) P[r * 4 + c] = K0[r * 3 + c];
        P[r * 4 + 3] = 0.0f;
    }
#pragma unroll
    for (int r = 0; r < 3; r++)
#pragma unroll
        for (int c = 0; c < 4; c++)
            P[12 + r * 4 + c] = fmaf(K1[r * 3 + 0], T[c],
                                fmaf(K1[r * 3 + 1], T[4 + c],
                                     K1[r * 3 + 2] * T[8 + c]));

    PtState S[ILP];
#pragma unroll
    for (int i = 0; i < ILP; i++) init_state(S[i], P, p0[i], p1[i], cf[i]);

    const int PP[6] = {0, 0, 0, 1, 1, 2};
    const int QQ[6] = {1, 2, 3, 2, 3, 3};
#pragma unroll 1
    for (int sw = 0; sw < NSWEEPS; sw++) {
#pragma unroll
        for (int pi = 0; pi < 6; pi++) {
#pragma unroll
            for (int i = 0; i < ILP; i++)           // 4 independent chains —
                jacobi_rot(S[i], PP[pi], QQ[pi]);   // scheduler interleaves them
        }
    }

    float val[ILP];
#pragma unroll
    for (int i = 0; i < ILP; i++) val[i] = finalize(S[i]);

    if (full) {
        *reinterpret_cast<float4*>(out + HW_IMG + n0) =
            make_float4(val[0], val[1], val[2], val[3]);
    } else {
#pragma unroll
        for (int i = 0; i < ILP; i++)
            if (n0 + i < N) out[HW_IMG + n0 + i] = val[i];
    }

    // Sparse-depth scatter, last-write-wins via 64-bit max keyed on index.
#pragma unroll
    for (int i = 0; i < ILP; i++) {
        if (n0 + i < N) {
            int xi = (int)p0[i].x, yi = (int)p0[i].y;  // trunc == astype(int32), x>=0
            unsigned long long pk =
                ((unsigned long long)(unsigned)(n0 + i + 1) << 32) |
                (unsigned)__float_as_uint(val[i]);
            atomicMax(&g_pack[yi * W_IMG + xi], pk);
        }
    }
}

// Streaming resolve: 2 pixels/thread (16B load, 8B store, 16B reset).
__global__ void __launch_bounds__(256)
resolve_kernel(float* __restrict__ out) {
    int i2 = (blockIdx.x * blockDim.x + threadIdx.x) * 2;
    if (i2 < HW_IMG) {
        ulonglong2 a = *reinterpret_cast<const ulonglong2*>(g_pack + i2);
        float2 o;
        o.x = __uint_as_float((unsigned)(a.x & 0xFFFFFFFFu));
        o.y = __uint_as_float((unsigned)(a.y & 0xFFFFFFFFu));
        *reinterpret_cast<float2*>(out + i2) = o;
        *reinterpret_cast<ulonglong2*>(g_pack + i2) = make_ulonglong2(0ull, 0ull);
    }
}

extern "C" void kernel_launch(void* const* d_in, const int* in_sizes, int n_in,
                              void* d_out, int out_size) {
    const float* T     = (const float*)d_in[0];  // [1,4,4]
    const float* K0    = (const float*)d_in[1];  // [1,3,3]
    const float* K1    = (const float*)d_in[2];  // [1,3,3]
    const float* mconf = (const float*)d_in[3];  // [N]
    const float* kp0   = (const float*)d_in[4];  // [N,2]
    const float* kp1   = (const float*)d_in[5];  // [N,2]
    // d_in[6] = image0 (fixed 480x640), d_in[7] = m_bids (all zero, single batch)
    int N = in_sizes[3];
    float* out = (float*)d_out;  // [HW_IMG depth | N kp3d_val]

    int threads = (N + ILP - 1) / ILP;
    tri_kernel<<<(threads + 127) / 128, 128>>>(T, K0, K1, mconf, kp0, kp1, out, N);
    resolve_kernel<<<(HW_IMG / 2 + 255) / 256, 256>>>(out);
}